// round 1
// baseline (speedup 1.0000x reference)
#include <cuda_runtime.h>

// Problem constants
#define BB    4
#define NPTS  16384
#define CI1   64
#define CO    128
#define RR    32
#define RR2   (RR*RR)
#define R3    (RR*RR*RR)
#define NVOX  (BB*R3)

// ---------------- device scratch (no allocations allowed) ----------------
__device__ float g_stat[BB][4];                    // mean x,y,z, denom
__device__ float g_cnt[NVOX];
__device__ float g_sums[(size_t)NVOX*CI1];         // voxel grid (Cin)   ~33.5MB
__device__ float g_grid1[(size_t)NVOX*CO];         // after conv1        ~67MB
__device__ float g_grid2[(size_t)NVOX*CO];         // after conv2        ~67MB

// ---------------- helpers ----------------
__device__ __forceinline__ unsigned long long ffma2(unsigned long long a,
                                                    unsigned long long b,
                                                    unsigned long long c) {
    unsigned long long d;
    asm("fma.rn.f32x2 %0, %1, %2, %3;" : "=l"(d) : "l"(a), "l"(b), "l"(c));
    return d;
}

__device__ __forceinline__ unsigned long long pack2(float a) {
    unsigned long long d;
    asm("mov.b64 %0, {%1, %1};" : "=l"(d) : "r"(__float_as_uint(a)));
    return d;
}

__device__ __forceinline__ float3 compute_nc(const float* cp, int b) {
    float mx = g_stat[b][0], my = g_stat[b][1], mz = g_stat[b][2];
    float denom = g_stat[b][3];
    float nx = ((cp[0] - mx) / denom + 0.5f) * (float)RR;
    float ny = ((cp[1] - my) / denom + 0.5f) * (float)RR;
    float nz = ((cp[2] - mz) / denom + 0.5f) * (float)RR;
    nx = fminf(fmaxf(nx, 0.f), (float)(RR - 1));
    ny = fminf(fmaxf(ny, 0.f), (float)(RR - 1));
    nz = fminf(fmaxf(nz, 0.f), (float)(RR - 1));
    return make_float3(nx, ny, nz);
}

// ---------------- 1. per-batch stats: mean + max-norm denom ----------------
__global__ void stats_kernel(const float* __restrict__ coords) {
    int b = blockIdx.x;
    const float* c = coords + (size_t)b * NPTS * 3;
    float sx = 0.f, sy = 0.f, sz = 0.f;
    for (int i = threadIdx.x; i < NPTS; i += blockDim.x) {
        sx += c[3 * i + 0];
        sy += c[3 * i + 1];
        sz += c[3 * i + 2];
    }
    __shared__ float red[4][32];
    int lane = threadIdx.x & 31, w = threadIdx.x >> 5;
    for (int o = 16; o; o >>= 1) {
        sx += __shfl_down_sync(0xffffffffu, sx, o);
        sy += __shfl_down_sync(0xffffffffu, sy, o);
        sz += __shfl_down_sync(0xffffffffu, sz, o);
    }
    if (lane == 0) { red[0][w] = sx; red[1][w] = sy; red[2][w] = sz; }
    __syncthreads();
    int nw = blockDim.x >> 5;
    if (threadIdx.x == 0) {
        float tx = 0.f, ty = 0.f, tz = 0.f;
        for (int i = 0; i < nw; i++) { tx += red[0][i]; ty += red[1][i]; tz += red[2][i]; }
        red[0][0] = tx / (float)NPTS;
        red[1][0] = ty / (float)NPTS;
        red[2][0] = tz / (float)NPTS;
    }
    __syncthreads();
    float mx = red[0][0], my = red[1][0], mz = red[2][0];
    float mval = 0.f;
    for (int i = threadIdx.x; i < NPTS; i += blockDim.x) {
        float dx = c[3 * i + 0] - mx;
        float dy = c[3 * i + 1] - my;
        float dz = c[3 * i + 2] - mz;
        mval = fmaxf(mval, sqrtf(dx * dx + dy * dy + dz * dz));
    }
    for (int o = 16; o; o >>= 1)
        mval = fmaxf(mval, __shfl_down_sync(0xffffffffu, mval, o));
    if (lane == 0) red[3][w] = mval;
    __syncthreads();
    if (threadIdx.x == 0) {
        float t = 0.f;
        for (int i = 0; i < nw; i++) t = fmaxf(t, red[3][i]);
        g_stat[b][0] = mx; g_stat[b][1] = my; g_stat[b][2] = mz;
        g_stat[b][3] = t * 2.f + 1e-6f;
    }
}

// ---------------- 2. zero scratch ----------------
__global__ void zero_kernel() {
    size_t stride = (size_t)gridDim.x * blockDim.x;
    size_t tid = (size_t)blockIdx.x * blockDim.x + threadIdx.x;
    float4 z4 = make_float4(0.f, 0.f, 0.f, 0.f);
    float4* s4 = (float4*)g_sums;
    for (size_t i = tid; i < (size_t)NVOX * (CI1 / 4); i += stride) s4[i] = z4;
    for (size_t i = tid; i < (size_t)NVOX; i += stride) g_cnt[i] = 0.f;
}

// ---------------- 3. scatter (atomic add) ----------------
__global__ void scatter_kernel(const float* __restrict__ feat,
                               const float* __restrict__ coords) {
    int gid = blockIdx.x * blockDim.x + threadIdx.x;
    if (gid >= BB * NPTS * 4) return;
    int pt = gid >> 2, q = gid & 3;
    int b = pt / NPTS;
    float3 nc = compute_nc(coords + (size_t)pt * 3, b);
    int vx = __float2int_rn(nc.x);
    int vy = __float2int_rn(nc.y);
    int vz = __float2int_rn(nc.z);
    int lin = b * R3 + vx * RR2 + vy * RR + vz;
    const float4* f = (const float4*)(feat + (size_t)pt * CI1 + q * 16);
    float* dst = g_sums + (size_t)lin * CI1 + q * 16;
#pragma unroll
    for (int j = 0; j < 4; j++) {
        float4 v = __ldg(f + j);
        atomicAdd(dst + 4 * j + 0, v.x);
        atomicAdd(dst + 4 * j + 1, v.y);
        atomicAdd(dst + 4 * j + 2, v.z);
        atomicAdd(dst + 4 * j + 3, v.w);
    }
    if (q == 0) atomicAdd(g_cnt + lin, 1.f);
}

// ---------------- 4. divide sums by counts ----------------
__global__ void finalize_kernel() {
    size_t stride = (size_t)gridDim.x * blockDim.x;
    size_t total = (size_t)NVOX * (CI1 / 4);
    for (size_t i = (size_t)blockIdx.x * blockDim.x + threadIdx.x; i < total; i += stride) {
        float cn = g_cnt[i >> 4];
        if (cn > 0.f) {
            float4* p = ((float4*)g_sums) + i;
            float4 v = *p;
            v.x /= cn; v.y /= cn; v.z /= cn; v.w /= cn;
            *p = v;
        }
    }
}

// ---------------- 5/6. Conv3D 3x3x3 + bias + BN + LeakyReLU ----------------
// Block: fixed (b,x,y) pencil; 128 threads = 32 z * 4 cout-groups of 32.
// Inner math uses packed fma.rn.f32x2 (2 FLOPs/lane/inst).
#define S_IN_ELEMS 5204      // 3*3*34*17 = 5202, padded for 16B alignment
#define S_W_ELEMS  2048      // 16 cin * 128 cout

template <int CI>
__device__ __forceinline__ void conv_body(
    const float* __restrict__ in, const float* __restrict__ w,
    const float* __restrict__ cb, const float* __restrict__ bg,
    const float* __restrict__ bb, const float* __restrict__ bm,
    const float* __restrict__ bv, float* __restrict__ outp) {
    __shared__ float s_in[S_IN_ELEMS];
    __shared__ float s_w[S_W_ELEMS];

    int x = blockIdx.x, y = blockIdx.y, b = blockIdx.z;
    int t = threadIdx.x;
    int zi = t & 31, cg = t >> 5;
    const size_t base_b = (size_t)b * R3;

    unsigned long long acc[16];
#pragma unroll
    for (int p = 0; p < 16; p++) acc[p] = 0ull;

    for (int cc = 0; cc < CI / 16; cc++) {
        __syncthreads();   // prior tap's compute finished before overwriting s_in
        // ---- stage input pencil tile: [3dx][3dy][34z][16cin], stride 17 ----
        for (int i = t; i < 9 * 34 * 4; i += 128) {
            int c4 = i & 3;
            int rem = i >> 2;
            int tz = rem % 34;
            int dxy = rem / 34;
            int dx = dxy / 3, dy = dxy % 3;
            int gx = x + dx - 1, gy = y + dy - 1, gz = tz - 1;
            float4 v = make_float4(0.f, 0.f, 0.f, 0.f);
            if (gx >= 0 && gx < RR && gy >= 0 && gy < RR && gz >= 0 && gz < RR) {
                size_t vidx = base_b + (size_t)(gx * RR2 + gy * RR + gz);
                v = __ldg((const float4*)(in + vidx * CI + cc * 16) + c4);
            }
            float* dst = &s_in[(dxy * 34 + tz) * 17 + c4 * 4];
            dst[0] = v.x; dst[1] = v.y; dst[2] = v.z; dst[3] = v.w;
        }
        for (int tap = 0; tap < 27; tap++) {
            __syncthreads();   // s_in ready (first tap) / prev tap compute done
            // ---- stage weights [16 cin][128 cout] (contiguous in source) ----
            const float4* wsrc = (const float4*)(w + ((size_t)tap * CI + cc * 16) * CO);
            for (int i = t; i < 512; i += 128)
                ((float4*)s_w)[i] = __ldg(wsrc + i);
            __syncthreads();

            int dxy = tap / 3;
            int dz = tap - dxy * 3;
            const float* inrow = &s_in[(dxy * 34 + zi + dz) * 17];
#pragma unroll
            for (int ci = 0; ci < 16; ci++) {
                unsigned long long av = pack2(inrow[ci]);
                const ulonglong2* w2 = (const ulonglong2*)&s_w[ci * CO + cg * 32];
#pragma unroll
                for (int j = 0; j < 8; j++) {
                    ulonglong2 p = w2[j];
                    acc[2 * j]     = ffma2(av, p.x, acc[2 * j]);
                    acc[2 * j + 1] = ffma2(av, p.y, acc[2 * j + 1]);
                }
            }
        }
    }

    // ---- epilogue: bias + BN fold + LeakyReLU ----
    size_t ovox = base_b + (size_t)(x * RR2 + y * RR + zi);
    float* op = outp + ovox * CO;
#pragma unroll
    for (int p = 0; p < 16; p++) {
        union { unsigned long long u; float2 f; } cvt;
        cvt.u = acc[p];
        int cbase = cg * 32 + ((p >> 1) << 2) + ((p & 1) << 1);
#pragma unroll
        for (int h = 0; h < 2; h++) {
            int co = cbase + h;
            float s = bg[co] * rsqrtf(bv[co] + 1e-4f);
            float sh = (cb[co] - bm[co]) * s + bb[co];
            float val = (h ? cvt.f.y : cvt.f.x) * s + sh;
            op[co] = val >= 0.f ? val : 0.1f * val;
        }
    }
}

__global__ void __launch_bounds__(128) conv1_kernel(
    const float* __restrict__ w, const float* __restrict__ cb,
    const float* __restrict__ bg, const float* __restrict__ bb,
    const float* __restrict__ bm, const float* __restrict__ bv) {
    conv_body<CI1>(g_sums, w, cb, bg, bb, bm, bv, g_grid1);
}

__global__ void __launch_bounds__(128) conv2_kernel(
    const float* __restrict__ w, const float* __restrict__ cb,
    const float* __restrict__ bg, const float* __restrict__ bb,
    const float* __restrict__ bm, const float* __restrict__ bv) {
    conv_body<CO>(g_grid1, w, cb, bg, bb, bm, bv, g_grid2);
}

// ---------------- 7. devoxelize + point MLP + add ----------------
__global__ void devox_kernel(const float* __restrict__ coords,
                             const float* __restrict__ feat,
                             const float* __restrict__ pw,
                             const float* __restrict__ pb,
                             const float* __restrict__ pg,
                             const float* __restrict__ pbb,
                             const float* __restrict__ pm,
                             const float* __restrict__ pv,
                             float* __restrict__ out) {
    int warp = blockIdx.x * (blockDim.x >> 5) + (threadIdx.x >> 5);
    int lane = threadIdx.x & 31;
    if (warp >= BB * NPTS) return;
    int b = warp / NPTS;
    float3 nc = compute_nc(coords + (size_t)warp * 3, b);
    int c0x = (int)floorf(nc.x);
    int c0y = (int)floorf(nc.y);
    int c0z = (int)floorf(nc.z);
    float fx = nc.x - (float)c0x;
    float fy = nc.y - (float)c0y;
    float fz = nc.z - (float)c0z;
    int c1x = min(c0x + 1, RR - 1);
    int c1y = min(c0y + 1, RR - 1);
    int c1z = min(c0z + 1, RR - 1);

    float4 acc = make_float4(0.f, 0.f, 0.f, 0.f);
    const float* gb = g_grid2 + (size_t)b * R3 * CO;
#pragma unroll
    for (int corner = 0; corner < 8; corner++) {
        int ix = (corner & 4) ? c1x : c0x;
        int iy = (corner & 2) ? c1y : c0y;
        int iz = (corner & 1) ? c1z : c0z;
        float wg = ((corner & 4) ? fx : 1.f - fx) *
                   ((corner & 2) ? fy : 1.f - fy) *
                   ((corner & 1) ? fz : 1.f - fz);
        float4 gv = __ldg((const float4*)(gb + (size_t)(ix * RR2 + iy * RR + iz) * CO) + lane);
        acc.x += wg * gv.x; acc.y += wg * gv.y;
        acc.z += wg * gv.z; acc.w += wg * gv.w;
    }

    float4 pacc = make_float4(0.f, 0.f, 0.f, 0.f);
    const float* fp = feat + (size_t)warp * CI1;
#pragma unroll 8
    for (int k = 0; k < CI1; k++) {
        float fv = __ldg(fp + k);
        float4 w4 = __ldg((const float4*)(pw + (size_t)k * CO) + lane);
        pacc.x += fv * w4.x; pacc.y += fv * w4.y;
        pacc.z += fv * w4.z; pacc.w += fv * w4.w;
    }

    float pr[4] = {pacc.x, pacc.y, pacc.z, pacc.w};
    float vr[4] = {acc.x, acc.y, acc.z, acc.w};
    float4 o;
#pragma unroll
    for (int j = 0; j < 4; j++) {
        int co = lane * 4 + j;
        float s = pg[co] * rsqrtf(pv[co] + 1e-5f);
        float val = (pr[j] + pb[co] - pm[co]) * s + pbb[co];
        val = fmaxf(val, 0.f);
        ((float*)&o)[j] = vr[j] + val;
    }
    *((float4*)(out + (size_t)warp * CO) + lane) = o;
}

// ---------------- 8. copy coords to output tail ----------------
__global__ void copy_coords_kernel(const float* __restrict__ c, float* __restrict__ out) {
    int i = blockIdx.x * blockDim.x + threadIdx.x;
    if (i < BB * NPTS * 3) out[i] = c[i];
}

// ---------------- launch ----------------
extern "C" void kernel_launch(void* const* d_in, const int* in_sizes, int n_in,
                              void* d_out, int out_size) {
    const float* feat   = (const float*)d_in[0];
    const float* coords = (const float*)d_in[1];
    const float* c1w = (const float*)d_in[2];
    const float* c1b = (const float*)d_in[3];
    const float* b1g = (const float*)d_in[4];
    const float* b1b = (const float*)d_in[5];
    const float* b1m = (const float*)d_in[6];
    const float* b1v = (const float*)d_in[7];
    const float* c2w = (const float*)d_in[8];
    const float* c2b = (const float*)d_in[9];
    const float* b2g = (const float*)d_in[10];
    const float* b2b = (const float*)d_in[11];
    const float* b2m = (const float*)d_in[12];
    const float* b2v = (const float*)d_in[13];
    const float* pw  = (const float*)d_in[14];
    const float* pb  = (const float*)d_in[15];
    const float* pg  = (const float*)d_in[16];
    const float* pbb = (const float*)d_in[17];
    const float* pm  = (const float*)d_in[18];
    const float* pv  = (const float*)d_in[19];
    float* out = (float*)d_out;

    stats_kernel<<<BB, 256>>>(coords);
    zero_kernel<<<2048, 256>>>();
    scatter_kernel<<<(BB * NPTS * 4 + 255) / 256, 256>>>(feat, coords);
    finalize_kernel<<<2048, 256>>>();
    conv1_kernel<<<dim3(RR, RR, BB), 128>>>(c1w, c1b, b1g, b1b, b1m, b1v);
    conv2_kernel<<<dim3(RR, RR, BB), 128>>>(c2w, c2b, b2g, b2b, b2m, b2v);
    devox_kernel<<<(BB * NPTS) / 8, 256>>>(coords, feat, pw, pb, pg, pbb, pm, pv, out);
    copy_coords_kernel<<<(BB * NPTS * 3 + 255) / 256, 256>>>(
        coords, out + (size_t)BB * NPTS * CO);
}

// round 5
// speedup vs baseline: 7.0133x; 7.0133x over previous
#include <cuda_runtime.h>
#include <cuda_fp16.h>
#include <cstdint>

// ---------------- problem constants ----------------
#define BB    4
#define NPTS  16384
#define CI1   64
#define CO    128
#define RR    32
#define RR2   (RR*RR)
#define R3    (RR*RR*RR)
#define NVOX  (BB*R3)

// ---------------- conv tiling ----------------
#define NST        3
#define APITCH     40                       // halves per smem row (80B, 16B-aligned, conflict-free)
#define STAGE_A    (128 * APITCH * 2)       // 10240 B
#define STAGE_BYTES (2 * STAGE_A)           // 20480 B (A + B)
#define DSMEM      (NST * STAGE_BYTES)      // 61440 B

// ---------------- device scratch ----------------
__device__ __align__(1024) float  g_stat[BB][4];
__device__ __align__(1024) float  g_cnt[NVOX];
__device__ __align__(1024) float  g_sums[(size_t)NVOX * CI1];     // fp32 scatter target
__device__ __align__(1024) __half g_sums_h[(size_t)NVOX * CI1];   // fp16 conv1 input
__device__ __align__(1024) __half g_w1h[27 * CO * CI1];           // [tap][co][ci] fp16
__device__ __align__(1024) __half g_w2h[27 * CO * CO];
__device__ __align__(1024) __half g_grid1h[(size_t)NVOX * CO];    // conv1 out (fp16)
__device__ __align__(1024) float  g_grid2[(size_t)NVOX * CO];     // conv2 out (fp32)

// ---------------- PTX helpers ----------------
__device__ __forceinline__ uint32_t smem_u32(const void* p) {
    uint32_t a;
    asm("{ .reg .u64 t; cvta.to.shared.u64 t, %1; cvt.u32.u64 %0, t; }" : "=r"(a) : "l"(p));
    return a;
}

__device__ __forceinline__ void cp_async16(uint32_t dst, const void* src, uint32_t sz) {
    asm volatile("cp.async.cg.shared.global [%0], [%1], 16, %2;"
                 :: "r"(dst), "l"(src), "r"(sz) : "memory");
}
#define CP_COMMIT() asm volatile("cp.async.commit_group;" ::: "memory")
#define CP_WAIT1()  asm volatile("cp.async.wait_group 1;" ::: "memory")

__device__ __forceinline__ uint32_t lds32(uint32_t addr) {
    uint32_t v;
    asm volatile("ld.shared.b32 %0, [%1];" : "=r"(v) : "r"(addr));
    return v;
}

__device__ __forceinline__ void mma16816(float* d, const uint32_t* a, const uint32_t* b) {
    asm volatile(
        "mma.sync.aligned.m16n8k16.row.col.f32.f16.f16.f32 "
        "{%0,%1,%2,%3}, {%4,%5,%6,%7}, {%8,%9}, {%0,%1,%2,%3};"
        : "+f"(d[0]), "+f"(d[1]), "+f"(d[2]), "+f"(d[3])
        : "r"(a[0]), "r"(a[1]), "r"(a[2]), "r"(a[3]), "r"(b[0]), "r"(b[1]));
}

// ---------------- nc helper ----------------
__device__ __forceinline__ float3 compute_nc(const float* cp, int b) {
    float denom = g_stat[b][3];
    float nx = ((cp[0] - g_stat[b][0]) / denom + 0.5f) * (float)RR;
    float ny = ((cp[1] - g_stat[b][1]) / denom + 0.5f) * (float)RR;
    float nz = ((cp[2] - g_stat[b][2]) / denom + 0.5f) * (float)RR;
    nx = fminf(fmaxf(nx, 0.f), (float)(RR - 1));
    ny = fminf(fmaxf(ny, 0.f), (float)(RR - 1));
    nz = fminf(fmaxf(nz, 0.f), (float)(RR - 1));
    return make_float3(nx, ny, nz);
}

// ---------------- 1. stats ----------------
__global__ void stats_kernel(const float* __restrict__ coords) {
    int b = blockIdx.x;
    const float* c = coords + (size_t)b * NPTS * 3;
    float sx = 0.f, sy = 0.f, sz = 0.f;
    for (int i = threadIdx.x; i < NPTS; i += blockDim.x) {
        sx += c[3 * i + 0]; sy += c[3 * i + 1]; sz += c[3 * i + 2];
    }
    __shared__ float red[4][32];
    int lane = threadIdx.x & 31, w = threadIdx.x >> 5;
    for (int o = 16; o; o >>= 1) {
        sx += __shfl_down_sync(0xffffffffu, sx, o);
        sy += __shfl_down_sync(0xffffffffu, sy, o);
        sz += __shfl_down_sync(0xffffffffu, sz, o);
    }
    if (lane == 0) { red[0][w] = sx; red[1][w] = sy; red[2][w] = sz; }
    __syncthreads();
    int nw = blockDim.x >> 5;
    if (threadIdx.x == 0) {
        float tx = 0.f, ty = 0.f, tz = 0.f;
        for (int i = 0; i < nw; i++) { tx += red[0][i]; ty += red[1][i]; tz += red[2][i]; }
        red[0][0] = tx / (float)NPTS; red[1][0] = ty / (float)NPTS; red[2][0] = tz / (float)NPTS;
    }
    __syncthreads();
    float mx = red[0][0], my = red[1][0], mz = red[2][0];
    float mval = 0.f;
    for (int i = threadIdx.x; i < NPTS; i += blockDim.x) {
        float dx = c[3 * i + 0] - mx, dy = c[3 * i + 1] - my, dz = c[3 * i + 2] - mz;
        mval = fmaxf(mval, sqrtf(dx * dx + dy * dy + dz * dz));
    }
    for (int o = 16; o; o >>= 1)
        mval = fmaxf(mval, __shfl_down_sync(0xffffffffu, mval, o));
    if (lane == 0) red[3][w] = mval;
    __syncthreads();
    if (threadIdx.x == 0) {
        float t = 0.f;
        for (int i = 0; i < nw; i++) t = fmaxf(t, red[3][i]);
        g_stat[b][0] = mx; g_stat[b][1] = my; g_stat[b][2] = mz;
        g_stat[b][3] = t * 2.f + 1e-6f;
    }
}

// ---------------- 2. zero ----------------
__global__ void zero_kernel() {
    size_t stride = (size_t)gridDim.x * blockDim.x;
    size_t tid = (size_t)blockIdx.x * blockDim.x + threadIdx.x;
    float4 z4 = make_float4(0.f, 0.f, 0.f, 0.f);
    float4* s4 = (float4*)g_sums;
    for (size_t i = tid; i < (size_t)NVOX * (CI1 / 4); i += stride) s4[i] = z4;
    for (size_t i = tid; i < (size_t)NVOX; i += stride) g_cnt[i] = 0.f;
}

// ---------------- 3. scatter ----------------
__global__ void scatter_kernel(const float* __restrict__ feat,
                               const float* __restrict__ coords) {
    int gid = blockIdx.x * blockDim.x + threadIdx.x;
    if (gid >= BB * NPTS * 4) return;
    int pt = gid >> 2, q = gid & 3;
    int b = pt / NPTS;
    float3 nc = compute_nc(coords + (size_t)pt * 3, b);
    int vx = __float2int_rn(nc.x), vy = __float2int_rn(nc.y), vz = __float2int_rn(nc.z);
    int lin = b * R3 + vx * RR2 + vy * RR + vz;
    const float4* f = (const float4*)(feat + (size_t)pt * CI1 + q * 16);
    float* dst = g_sums + (size_t)lin * CI1 + q * 16;
#pragma unroll
    for (int j = 0; j < 4; j++) {
        float4 v = __ldg(f + j);
        atomicAdd(dst + 4 * j + 0, v.x);
        atomicAdd(dst + 4 * j + 1, v.y);
        atomicAdd(dst + 4 * j + 2, v.z);
        atomicAdd(dst + 4 * j + 3, v.w);
    }
    if (q == 0) atomicAdd(g_cnt + lin, 1.f);
}

// ---------------- 4. finalize: divide + fp16 convert ----------------
__global__ void finalize_kernel() {
    size_t stride = (size_t)gridDim.x * blockDim.x;
    size_t total = (size_t)NVOX * (CI1 / 4);
    __half2* oh = (__half2*)g_sums_h;
    for (size_t i = (size_t)blockIdx.x * blockDim.x + threadIdx.x; i < total; i += stride) {
        float cn = g_cnt[i >> 4];
        float inv = cn > 0.f ? 1.f / cn : 1.f;
        float4 v = ((float4*)g_sums)[i];
        oh[2 * i + 0] = __floats2half2_rn(v.x * inv, v.y * inv);
        oh[2 * i + 1] = __floats2half2_rn(v.z * inv, v.w * inv);
    }
}

// ---------------- 5. weight prep: [tap][ci][co] -> [tap][co][ci] fp16 ----------------
template <int CI>
__global__ void wprep_kernel(const float* __restrict__ w, __half* __restrict__ wt) {
    int idx = blockIdx.x * blockDim.x + threadIdx.x;
    if (idx >= 27 * CI * CO) return;
    int t = idx / (CI * CO);
    int rem = idx - t * (CI * CO);
    int co = rem / CI;
    int ci = rem - co * CI;
    wt[idx] = __float2half_rn(__ldg(&w[((size_t)t * CI + ci) * CO + co]));
}

// ---------------- 6. fp16 mma.sync implicit-GEMM Conv3D ----------------
// CTA = 256 thr (8 warps, 2Mx4N), tile M=128 voxels (x fixed, 4y x 32z), N=128 cout.
// K = 27 taps x (CI/32) chunks; per step cp.async-stage A(128x32 h) + B(128x32 h),
// 3-stage ring; halo via zfill. Epilogue: bias+BN fold + LeakyReLU.
template <int CI, bool FIRST>
__global__ void __launch_bounds__(256) conv_mma_kernel(
    const float* __restrict__ cb, const float* __restrict__ bg,
    const float* __restrict__ bb, const float* __restrict__ bm,
    const float* __restrict__ bv) {
    constexpr int KC = CI / 32;
    constexpr int S = 27 * KC;
    const __half* in = FIRST ? g_sums_h : g_grid1h;
    const __half* wt = FIRST ? g_w1h : g_w2h;

    extern __shared__ char dsm[];
    __shared__ float s_scale[CO], s_shift[CO];

    int tid = threadIdx.x, lane = tid & 31, wid = tid >> 5;
    int gID = lane >> 2, tig = lane & 3;
    int wm = wid >> 2, wn = wid & 3;
    int x = blockIdx.x, y0 = blockIdx.y * 4, b = blockIdx.z;
    size_t bbase = (size_t)b * R3;

    if (tid < CO) {
        float s = bg[tid] * rsqrtf(bv[tid] + 1e-4f);
        s_scale[tid] = s;
        s_shift[tid] = (cb[tid] - bm[tid]) * s + bb[tid];
    }

    uint32_t sb = smem_u32(dsm);

    auto issue = [&](int p) {
        int buf = p % NST;
        int tap = p / KC, cc = p - tap * KC;
        int dx = tap / 9, dyz = tap - dx * 9, dy = dyz / 3, dz = dyz - dy * 3;
        int gx = x + dx - 1;
        bool xok = ((unsigned)gx < RR);
        int gxc = xok ? gx : 0;
        uint32_t aB = sb + buf * STAGE_BYTES;
        uint32_t bB = aB + STAGE_A;
#pragma unroll
        for (int it = 0; it < 2; it++) {
            int i = tid + it * 256;
            int row = i >> 2, c4 = i & 3;
            int yy = row >> 5, z = row & 31;
            int gy = y0 + yy + dy - 1, gz = z + dz - 1;
            bool ok = xok && ((unsigned)gy < RR) && ((unsigned)gz < RR);
            int gyc = ok ? gy : 0, gzc = ok ? gz : 0;
            const char* src = (const char*)(in +
                ((size_t)(bbase + gxc * RR2 + gyc * RR + gzc)) * CI + cc * 32) + c4 * 16;
            cp_async16(aB + row * (APITCH * 2) + c4 * 16, src, ok ? 16u : 0u);
        }
#pragma unroll
        for (int it = 0; it < 2; it++) {
            int i = tid + it * 256;
            int row = i >> 2, c4 = i & 3;
            const char* src = (const char*)(wt + ((size_t)tap * CO + row) * CI + cc * 32) + c4 * 16;
            cp_async16(bB + row * (APITCH * 2) + c4 * 16, src, 16u);
        }
        CP_COMMIT();
    };

    float d[4][4][4];
#pragma unroll
    for (int mt = 0; mt < 4; mt++)
#pragma unroll
        for (int nt = 0; nt < 4; nt++)
#pragma unroll
            for (int r = 0; r < 4; r++) d[mt][nt][r] = 0.f;

    issue(0);
    issue(1);
    for (int t = 0; t < S; t++) {
        CP_WAIT1();
        __syncthreads();
        if (t + 2 < S) issue(t + 2); else CP_COMMIT();
        uint32_t aB = sb + (t % NST) * STAGE_BYTES;
        uint32_t bB = aB + STAGE_A;
#pragma unroll
        for (int kt = 0; kt < 2; kt++) {
            uint32_t a[4][4], bf[4][2];
#pragma unroll
            for (int mt = 0; mt < 4; mt++) {
                uint32_t base = aB + ((wm * 64 + mt * 16 + gID) * APITCH + kt * 16 + 2 * tig) * 2;
                a[mt][0] = lds32(base);
                a[mt][1] = lds32(base + 8 * APITCH * 2);
                a[mt][2] = lds32(base + 16);
                a[mt][3] = lds32(base + 8 * APITCH * 2 + 16);
            }
#pragma unroll
            for (int nt = 0; nt < 4; nt++) {
                uint32_t base = bB + ((wn * 32 + nt * 8 + gID) * APITCH + kt * 16 + 2 * tig) * 2;
                bf[nt][0] = lds32(base);
                bf[nt][1] = lds32(base + 16);
            }
#pragma unroll
            for (int mt = 0; mt < 4; mt++)
#pragma unroll
                for (int nt = 0; nt < 4; nt++)
                    mma16816(d[mt][nt], a[mt], bf[nt]);
        }
    }

    // ---- epilogue ----
#pragma unroll
    for (int mt = 0; mt < 4; mt++) {
        int r0 = wm * 64 + mt * 16 + gID;
        int r1 = r0 + 8;
        size_t vox0 = bbase + (size_t)x * RR2 + (size_t)(y0 + (r0 >> 5)) * RR + (r0 & 31);
        size_t vox1 = bbase + (size_t)x * RR2 + (size_t)(y0 + (r1 >> 5)) * RR + (r1 & 31);
#pragma unroll
        for (int nt = 0; nt < 4; nt++) {
            int col = wn * 32 + nt * 8 + 2 * tig;
            float sc0 = s_scale[col], sh0 = s_shift[col];
            float sc1 = s_scale[col + 1], sh1 = s_shift[col + 1];
            float v00 = d[mt][nt][0] * sc0 + sh0;
            float v01 = d[mt][nt][1] * sc1 + sh1;
            float v10 = d[mt][nt][2] * sc0 + sh0;
            float v11 = d[mt][nt][3] * sc1 + sh1;
            v00 = v00 >= 0.f ? v00 : 0.1f * v00;
            v01 = v01 >= 0.f ? v01 : 0.1f * v01;
            v10 = v10 >= 0.f ? v10 : 0.1f * v10;
            v11 = v11 >= 0.f ? v11 : 0.1f * v11;
            if (FIRST) {
                *(__half2*)(g_grid1h + vox0 * CO + col) = __floats2half2_rn(v00, v01);
                *(__half2*)(g_grid1h + vox1 * CO + col) = __floats2half2_rn(v10, v11);
            } else {
                *(float2*)(g_grid2 + vox0 * CO + col) = make_float2(v00, v01);
                *(float2*)(g_grid2 + vox1 * CO + col) = make_float2(v10, v11);
            }
        }
    }
}

// ---------------- 7. devoxelize + point MLP ----------------
__global__ void devox_kernel(const float* __restrict__ coords,
                             const float* __restrict__ feat,
                             const float* __restrict__ pw,
                             const float* __restrict__ pb,
                             const float* __restrict__ pg,
                             const float* __restrict__ pbb,
                             const float* __restrict__ pm,
                             const float* __restrict__ pv,
                             float* __restrict__ out) {
    int warp = blockIdx.x * (blockDim.x >> 5) + (threadIdx.x >> 5);
    int lane = threadIdx.x & 31;
    if (warp >= BB * NPTS) return;
    int b = warp / NPTS;
    float3 nc = compute_nc(coords + (size_t)warp * 3, b);
    int c0x = (int)floorf(nc.x), c0y = (int)floorf(nc.y), c0z = (int)floorf(nc.z);
    float fx = nc.x - (float)c0x, fy = nc.y - (float)c0y, fz = nc.z - (float)c0z;
    int c1x = min(c0x + 1, RR - 1), c1y = min(c0y + 1, RR - 1), c1z = min(c0z + 1, RR - 1);

    float4 acc = make_float4(0.f, 0.f, 0.f, 0.f);
    const float* gb = g_grid2 + (size_t)b * R3 * CO;
#pragma unroll
    for (int corner = 0; corner < 8; corner++) {
        int ix = (corner & 4) ? c1x : c0x;
        int iy = (corner & 2) ? c1y : c0y;
        int iz = (corner & 1) ? c1z : c0z;
        float wg = ((corner & 4) ? fx : 1.f - fx) *
                   ((corner & 2) ? fy : 1.f - fy) *
                   ((corner & 1) ? fz : 1.f - fz);
        float4 gv = __ldg((const float4*)(gb + (size_t)(ix * RR2 + iy * RR + iz) * CO) + lane);
        acc.x += wg * gv.x; acc.y += wg * gv.y; acc.z += wg * gv.z; acc.w += wg * gv.w;
    }

    float4 pacc = make_float4(0.f, 0.f, 0.f, 0.f);
    const float* fp = feat + (size_t)warp * CI1;
#pragma unroll 8
    for (int k = 0; k < CI1; k++) {
        float fv = __ldg(fp + k);
        float4 w4 = __ldg((const float4*)(pw + (size_t)k * CO) + lane);
        pacc.x += fv * w4.x; pacc.y += fv * w4.y;
        pacc.z += fv * w4.z; pacc.w += fv * w4.w;
    }

    float pr[4] = {pacc.x, pacc.y, pacc.z, pacc.w};
    float vr[4] = {acc.x, acc.y, acc.z, acc.w};
    float4 o;
#pragma unroll
    for (int j = 0; j < 4; j++) {
        int co = lane * 4 + j;
        float s = pg[co] * rsqrtf(pv[co] + 1e-5f);
        float val = (pr[j] + pb[co] - pm[co]) * s + pbb[co];
        val = fmaxf(val, 0.f);
        ((float*)&o)[j] = vr[j] + val;
    }
    *((float4*)(out + (size_t)warp * CO) + lane) = o;
}

// ---------------- 8. coords tail copy ----------------
__global__ void copy_coords_kernel(const float* __restrict__ c, float* __restrict__ out) {
    int i = blockIdx.x * blockDim.x + threadIdx.x;
    if (i < BB * NPTS * 3) out[i] = c[i];
}

// ---------------- launch ----------------
extern "C" void kernel_launch(void* const* d_in, const int* in_sizes, int n_in,
                              void* d_out, int out_size) {
    const float* feat   = (const float*)d_in[0];
    const float* coords = (const float*)d_in[1];
    const float* c1w = (const float*)d_in[2];
    const float* c1b = (const float*)d_in[3];
    const float* b1g = (const float*)d_in[4];
    const float* b1b = (const float*)d_in[5];
    const float* b1m = (const float*)d_in[6];
    const float* b1v = (const float*)d_in[7];
    const float* c2w = (const float*)d_in[8];
    const float* c2b = (const float*)d_in[9];
    const float* b2g = (const float*)d_in[10];
    const float* b2b = (const float*)d_in[11];
    const float* b2m = (const float*)d_in[12];
    const float* b2v = (const float*)d_in[13];
    const float* pw  = (const float*)d_in[14];
    const float* pb  = (const float*)d_in[15];
    const float* pg  = (const float*)d_in[16];
    const float* pbb = (const float*)d_in[17];
    const float* pm  = (const float*)d_in[18];
    const float* pv  = (const float*)d_in[19];
    float* out = (float*)d_out;

    __half* pW1h;
    __half* pW2h;
    cudaGetSymbolAddress((void**)&pW1h, g_w1h);
    cudaGetSymbolAddress((void**)&pW2h, g_w2h);

    cudaFuncSetAttribute((const void*)conv_mma_kernel<CI1, true>,
                         cudaFuncAttributeMaxDynamicSharedMemorySize, DSMEM);
    cudaFuncSetAttribute((const void*)conv_mma_kernel<CO, false>,
                         cudaFuncAttributeMaxDynamicSharedMemorySize, DSMEM);

    stats_kernel<<<BB, 256>>>(coords);
    zero_kernel<<<2048, 256>>>();
    scatter_kernel<<<(BB * NPTS * 4 + 255) / 256, 256>>>(feat, coords);
    finalize_kernel<<<2048, 256>>>();
    wprep_kernel<CI1><<<(27 * CI1 * CO + 255) / 256, 256>>>(c1w, pW1h);
    wprep_kernel<CO><<<(27 * CO * CO + 255) / 256, 256>>>(c2w, pW2h);
    conv_mma_kernel<CI1, true><<<dim3(RR, RR / 4, BB), 256, DSMEM>>>(
        c1b, b1g, b1b, b1m, b1v);
    conv_mma_kernel<CO, false><<<dim3(RR, RR / 4, BB), 256, DSMEM>>>(
        c2b, b2g, b2b, b2m, b2v);
    devox_kernel<<<(BB * NPTS) / 8, 256>>>(coords, feat, pw, pb, pg, pbb, pm, pv, out);
    copy_coords_kernel<<<(BB * NPTS * 3 + 255) / 256, 256>>>(
        coords, out + (size_t)BB * NPTS * CO);
}

// round 6
// speedup vs baseline: 7.9055x; 1.1272x over previous
#include <cuda_runtime.h>
#include <cuda_fp16.h>
#include <cstdint>

// ---------------- problem constants ----------------
#define BB    4
#define NPTS  16384
#define CI1   64
#define CO    128
#define RR    32
#define RR2   (RR*RR)
#define R3    (RR*RR*RR)
#define NVOX  (BB*R3)

// ---------------- conv tiling ----------------
#define APITCH   40                         // halves per smem row (80B), conflict-free
#define AROWS    (3*6*34)                   // 612 halo rows (dx, y-halo, z-halo)
#define A_BYTES  (AROWS * APITCH * 2)       // 48960
#define B_STAGE  (128 * APITCH * 2)         // 10240
#define NBUF_B   4
#define DSMEM    (A_BYTES + NBUF_B * B_STAGE)   // 89920

// ---------------- device scratch ----------------
__device__ __align__(1024) float  g_stat[BB][4];
__device__ __align__(1024) float  g_cnt[NVOX];
__device__ __align__(1024) float  g_sums[(size_t)NVOX * CI1];     // fp32 scatter target
__device__ __align__(1024) __half g_sums_h[(size_t)NVOX * CI1];   // fp16 conv1 input
__device__ __align__(1024) __half g_w1h[27 * CO * CI1];           // [tap][co][ci] fp16
__device__ __align__(1024) __half g_w2h[27 * CO * CO];
__device__ __align__(1024) __half g_grid1h[(size_t)NVOX * CO];    // conv1 out (fp16)
__device__ __align__(1024) __half g_grid2h[(size_t)NVOX * CO];    // conv2 out (fp16)

// ---------------- PTX helpers ----------------
__device__ __forceinline__ uint32_t smem_u32(const void* p) {
    uint32_t a;
    asm("{ .reg .u64 t; cvta.to.shared.u64 t, %1; cvt.u32.u64 %0, t; }" : "=r"(a) : "l"(p));
    return a;
}

__device__ __forceinline__ void cp_async16(uint32_t dst, const void* src, uint32_t sz) {
    asm volatile("cp.async.cg.shared.global [%0], [%1], 16, %2;"
                 :: "r"(dst), "l"(src), "r"(sz) : "memory");
}
#define CP_COMMIT() asm volatile("cp.async.commit_group;" ::: "memory")
#define CP_WAIT0()  asm volatile("cp.async.wait_group 0;" ::: "memory")
#define CP_WAIT1()  asm volatile("cp.async.wait_group 1;" ::: "memory")
#define CP_WAIT2()  asm volatile("cp.async.wait_group 2;" ::: "memory")

__device__ __forceinline__ uint32_t lds32(uint32_t addr) {
    uint32_t v;
    asm volatile("ld.shared.b32 %0, [%1];" : "=r"(v) : "r"(addr));
    return v;
}

__device__ __forceinline__ void mma16816(float* d, const uint32_t* a, const uint32_t* b) {
    asm volatile(
        "mma.sync.aligned.m16n8k16.row.col.f32.f16.f16.f32 "
        "{%0,%1,%2,%3}, {%4,%5,%6,%7}, {%8,%9}, {%0,%1,%2,%3};"
        : "+f"(d[0]), "+f"(d[1]), "+f"(d[2]), "+f"(d[3])
        : "r"(a[0]), "r"(a[1]), "r"(a[2]), "r"(a[3]), "r"(b[0]), "r"(b[1]));
}

// ---------------- nc helper ----------------
__device__ __forceinline__ float3 compute_nc(const float* cp, int b) {
    float denom = g_stat[b][3];
    float nx = ((cp[0] - g_stat[b][0]) / denom + 0.5f) * (float)RR;
    float ny = ((cp[1] - g_stat[b][1]) / denom + 0.5f) * (float)RR;
    float nz = ((cp[2] - g_stat[b][2]) / denom + 0.5f) * (float)RR;
    nx = fminf(fmaxf(nx, 0.f), (float)(RR - 1));
    ny = fminf(fmaxf(ny, 0.f), (float)(RR - 1));
    nz = fminf(fmaxf(nz, 0.f), (float)(RR - 1));
    return make_float3(nx, ny, nz);
}

// ---------------- 1. stats ----------------
__global__ void stats_kernel(const float* __restrict__ coords) {
    int b = blockIdx.x;
    const float* c = coords + (size_t)b * NPTS * 3;
    float sx = 0.f, sy = 0.f, sz = 0.f;
    for (int i = threadIdx.x; i < NPTS; i += blockDim.x) {
        sx += c[3 * i + 0]; sy += c[3 * i + 1]; sz += c[3 * i + 2];
    }
    __shared__ float red[4][32];
    int lane = threadIdx.x & 31, w = threadIdx.x >> 5;
    for (int o = 16; o; o >>= 1) {
        sx += __shfl_down_sync(0xffffffffu, sx, o);
        sy += __shfl_down_sync(0xffffffffu, sy, o);
        sz += __shfl_down_sync(0xffffffffu, sz, o);
    }
    if (lane == 0) { red[0][w] = sx; red[1][w] = sy; red[2][w] = sz; }
    __syncthreads();
    int nw = blockDim.x >> 5;
    if (threadIdx.x == 0) {
        float tx = 0.f, ty = 0.f, tz = 0.f;
        for (int i = 0; i < nw; i++) { tx += red[0][i]; ty += red[1][i]; tz += red[2][i]; }
        red[0][0] = tx / (float)NPTS; red[1][0] = ty / (float)NPTS; red[2][0] = tz / (float)NPTS;
    }
    __syncthreads();
    float mx = red[0][0], my = red[1][0], mz = red[2][0];
    float mval = 0.f;
    for (int i = threadIdx.x; i < NPTS; i += blockDim.x) {
        float dx = c[3 * i + 0] - mx, dy = c[3 * i + 1] - my, dz = c[3 * i + 2] - mz;
        mval = fmaxf(mval, sqrtf(dx * dx + dy * dy + dz * dz));
    }
    for (int o = 16; o; o >>= 1)
        mval = fmaxf(mval, __shfl_down_sync(0xffffffffu, mval, o));
    if (lane == 0) red[3][w] = mval;
    __syncthreads();
    if (threadIdx.x == 0) {
        float t = 0.f;
        for (int i = 0; i < nw; i++) t = fmaxf(t, red[3][i]);
        g_stat[b][0] = mx; g_stat[b][1] = my; g_stat[b][2] = mz;
        g_stat[b][3] = t * 2.f + 1e-6f;
    }
}

// ---------------- 2. zero ----------------
__global__ void zero_kernel() {
    size_t stride = (size_t)gridDim.x * blockDim.x;
    size_t tid = (size_t)blockIdx.x * blockDim.x + threadIdx.x;
    float4 z4 = make_float4(0.f, 0.f, 0.f, 0.f);
    float4* s4 = (float4*)g_sums;
    for (size_t i = tid; i < (size_t)NVOX * (CI1 / 4); i += stride) s4[i] = z4;
    for (size_t i = tid; i < (size_t)NVOX; i += stride) g_cnt[i] = 0.f;
}

// ---------------- 3. scatter ----------------
__global__ void scatter_kernel(const float* __restrict__ feat,
                               const float* __restrict__ coords) {
    int gid = blockIdx.x * blockDim.x + threadIdx.x;
    if (gid >= BB * NPTS * 4) return;
    int pt = gid >> 2, q = gid & 3;
    int b = pt / NPTS;
    float3 nc = compute_nc(coords + (size_t)pt * 3, b);
    int vx = __float2int_rn(nc.x), vy = __float2int_rn(nc.y), vz = __float2int_rn(nc.z);
    int lin = b * R3 + vx * RR2 + vy * RR + vz;
    const float4* f = (const float4*)(feat + (size_t)pt * CI1 + q * 16);
    float* dst = g_sums + (size_t)lin * CI1 + q * 16;
#pragma unroll
    for (int j = 0; j < 4; j++) {
        float4 v = __ldg(f + j);
        atomicAdd(dst + 4 * j + 0, v.x);
        atomicAdd(dst + 4 * j + 1, v.y);
        atomicAdd(dst + 4 * j + 2, v.z);
        atomicAdd(dst + 4 * j + 3, v.w);
    }
    if (q == 0) atomicAdd(g_cnt + lin, 1.f);
}

// ---------------- 4. finalize: divide + fp16 convert ----------------
__global__ void finalize_kernel() {
    size_t stride = (size_t)gridDim.x * blockDim.x;
    size_t total = (size_t)NVOX * (CI1 / 4);
    __half2* oh = (__half2*)g_sums_h;
    for (size_t i = (size_t)blockIdx.x * blockDim.x + threadIdx.x; i < total; i += stride) {
        float cn = g_cnt[i >> 4];
        float inv = cn > 0.f ? 1.f / cn : 1.f;
        float4 v = ((float4*)g_sums)[i];
        oh[2 * i + 0] = __floats2half2_rn(v.x * inv, v.y * inv);
        oh[2 * i + 1] = __floats2half2_rn(v.z * inv, v.w * inv);
    }
}

// ---------------- 5. weight prep: [tap][ci][co] -> [tap][co][ci] fp16 ----------------
template <int CI>
__global__ void wprep_kernel(const float* __restrict__ w, __half* __restrict__ wt) {
    int idx = blockIdx.x * blockDim.x + threadIdx.x;
    if (idx >= 27 * CI * CO) return;
    int t = idx / (CI * CO);
    int rem = idx - t * (CI * CO);
    int co = rem / CI;
    int ci = rem - co * CI;
    wt[idx] = __float2half_rn(__ldg(&w[((size_t)t * CI + ci) * CO + co]));
}

// ---------------- 6. fp16 mma.sync implicit-GEMM Conv3D (halo-resident A) ----------------
// CTA = 256 thr (8 warps, 2Mx4N), tile M=128 voxels (x fixed, 4y x 32z), N=128 cout.
// Per ci-chunk: stage A halo (3dx x 6y x 34z x 32ci) ONCE, then 27 taps from smem.
// B [128co x 32ci] per tap, quad-buffered, depth-3 cp.async prefetch.
template <int CI, bool FIRST>
__global__ void __launch_bounds__(256, 2) conv_mma_kernel(
    const float* __restrict__ cb, const float* __restrict__ bg,
    const float* __restrict__ bb, const float* __restrict__ bm,
    const float* __restrict__ bv) {
    constexpr int KC = CI / 32;
    constexpr int S = 27 * KC;
    const __half* in = FIRST ? g_sums_h : g_grid1h;
    const __half* wt = FIRST ? g_w1h : g_w2h;

    extern __shared__ char dsm[];
    __shared__ float s_scale[CO], s_shift[CO];

    int tid = threadIdx.x, lane = tid & 31, wid = tid >> 5;
    int gID = lane >> 2, tig = lane & 3;
    int wm = wid >> 2, wn = wid & 3;
    int x = blockIdx.x, y0 = blockIdx.y * 4, b = blockIdx.z;
    size_t bbase = (size_t)b * R3;

    if (tid < CO) {
        float s = bg[tid] * rsqrtf(bv[tid] + 1e-4f);
        s_scale[tid] = s;
        s_shift[tid] = (cb[tid] - bm[tid]) * s + bb[tid];
    }

    uint32_t aB = smem_u32(dsm);
    uint32_t bB = aB + A_BYTES;

    // per-mt output row decode (tap-independent)
    int ry0[4], rz0[4], ry1[4], rz1[4];
#pragma unroll
    for (int mt = 0; mt < 4; mt++) {
        int r0 = wm * 64 + mt * 16 + gID;
        int r1 = r0 + 8;
        ry0[mt] = r0 >> 5; rz0[mt] = r0 & 31;
        ry1[mt] = r1 >> 5; rz1[mt] = r1 & 31;
    }

    auto issueA = [&](int cc) {
        for (int i = tid; i < AROWS * 4; i += 256) {
            int row = i >> 2, c4 = i & 3;
            int dxp = row / 204, rem = row - dxp * 204;
            int yl = rem / 34, zl = rem - yl * 34;
            int gx = x + dxp - 1, gy = y0 + yl - 1, gz = zl - 1;
            bool ok = ((unsigned)gx < RR) && ((unsigned)gy < RR) && ((unsigned)gz < RR);
            int gxc = ok ? gx : 0, gyc = ok ? gy : 0, gzc = ok ? gz : 0;
            const __half* src = in +
                ((size_t)(bbase + gxc * RR2 + gyc * RR + gzc)) * CI + cc * 32 + c4 * 8;
            cp_async16(aB + row * (APITCH * 2) + c4 * 16, src, ok ? 16u : 0u);
        }
        CP_COMMIT();
    };

    auto issueB = [&](int g) {
        int tap = g % 27, cc = g / 27;
        uint32_t dst = bB + (g & (NBUF_B - 1)) * B_STAGE;
#pragma unroll
        for (int it = 0; it < 2; it++) {
            int i = tid + it * 256;
            int row = i >> 2, c4 = i & 3;
            const __half* src = wt + ((size_t)tap * CO + row) * CI + cc * 32 + c4 * 8;
            cp_async16(dst + row * (APITCH * 2) + c4 * 16, src, 16u);
        }
        CP_COMMIT();
    };

    float d[4][4][4];
#pragma unroll
    for (int mt = 0; mt < 4; mt++)
#pragma unroll
        for (int nt = 0; nt < 4; nt++)
#pragma unroll
            for (int r = 0; r < 4; r++) d[mt][nt][r] = 0.f;

    // prologue: A(0), B(0), B(1), B(2)
    issueA(0);
    issueB(0); issueB(1); issueB(2);

    for (int g = 0; g < S; g++) {
        int tap = g % 27;
        if (tap == 0 && g > 0) {
            __syncthreads();              // all warps done with previous A chunk
            issueA(g / 27);
            CP_WAIT0();                   // A + all pending B complete (small bubble)
            __syncthreads();
        } else {
            if (g + 3 <= S - 1)      CP_WAIT2();
            else if (g + 2 <= S - 1) CP_WAIT1();
            else                     CP_WAIT0();
            __syncthreads();
        }
        if (g + 3 < S && (g + 3) % 27 != 0) issueB(g + 3);
        else if (g + 3 < S) issueB(g + 3);   // B is A-independent; always prefetch

        int dxp = tap / 9, dyz = tap - dxp * 9, dy = dyz / 3, dz = dyz - dy * 3;
        int arowbase = dxp * 204 + dy * 34 + dz;
        uint32_t bBuf = bB + (g & (NBUF_B - 1)) * B_STAGE;
#pragma unroll
        for (int kt = 0; kt < 2; kt++) {
            uint32_t a[4][4], bf[4][2];
#pragma unroll
            for (int mt = 0; mt < 4; mt++) {
                int arow0 = arowbase + ry0[mt] * 34 + rz0[mt];
                int arow1 = arowbase + ry1[mt] * 34 + rz1[mt];
                uint32_t b0 = aB + (arow0 * APITCH + kt * 16 + 2 * tig) * 2;
                uint32_t b1 = aB + (arow1 * APITCH + kt * 16 + 2 * tig) * 2;
                a[mt][0] = lds32(b0);
                a[mt][1] = lds32(b1);
                a[mt][2] = lds32(b0 + 16);
                a[mt][3] = lds32(b1 + 16);
            }
#pragma unroll
            for (int nt = 0; nt < 4; nt++) {
                uint32_t base = bBuf + ((wn * 32 + nt * 8 + gID) * APITCH + kt * 16 + 2 * tig) * 2;
                bf[nt][0] = lds32(base);
                bf[nt][1] = lds32(base + 16);
            }
#pragma unroll
            for (int mt = 0; mt < 4; mt++)
#pragma unroll
                for (int nt = 0; nt < 4; nt++)
                    mma16816(d[mt][nt], a[mt], bf[nt]);
        }
    }

    // ---- epilogue: bias+BN fold + LeakyReLU, fp16 store ----
    __half* outp = FIRST ? g_grid1h : g_grid2h;
#pragma unroll
    for (int mt = 0; mt < 4; mt++) {
        int r0 = wm * 64 + mt * 16 + gID;
        int r1 = r0 + 8;
        size_t vox0 = bbase + (size_t)x * RR2 + (size_t)(y0 + (r0 >> 5)) * RR + (r0 & 31);
        size_t vox1 = bbase + (size_t)x * RR2 + (size_t)(y0 + (r1 >> 5)) * RR + (r1 & 31);
#pragma unroll
        for (int nt = 0; nt < 4; nt++) {
            int col = wn * 32 + nt * 8 + 2 * tig;
            float sc0 = s_scale[col], sh0 = s_shift[col];
            float sc1 = s_scale[col + 1], sh1 = s_shift[col + 1];
            float v00 = d[mt][nt][0] * sc0 + sh0;
            float v01 = d[mt][nt][1] * sc1 + sh1;
            float v10 = d[mt][nt][2] * sc0 + sh0;
            float v11 = d[mt][nt][3] * sc1 + sh1;
            v00 = v00 >= 0.f ? v00 : 0.1f * v00;
            v01 = v01 >= 0.f ? v01 : 0.1f * v01;
            v10 = v10 >= 0.f ? v10 : 0.1f * v10;
            v11 = v11 >= 0.f ? v11 : 0.1f * v11;
            *(__half2*)(outp + vox0 * CO + col) = __floats2half2_rn(v00, v01);
            *(__half2*)(outp + vox1 * CO + col) = __floats2half2_rn(v10, v11);
        }
    }
}

// ---------------- 7. devoxelize + point MLP ----------------
__global__ void devox_kernel(const float* __restrict__ coords,
                             const float* __restrict__ feat,
                             const float* __restrict__ pw,
                             const float* __restrict__ pb,
                             const float* __restrict__ pg,
                             const float* __restrict__ pbb,
                             const float* __restrict__ pm,
                             const float* __restrict__ pv,
                             float* __restrict__ out) {
    int warp = blockIdx.x * (blockDim.x >> 5) + (threadIdx.x >> 5);
    int lane = threadIdx.x & 31;
    if (warp >= BB * NPTS) return;
    int b = warp / NPTS;
    float3 nc = compute_nc(coords + (size_t)warp * 3, b);
    int c0x = (int)floorf(nc.x), c0y = (int)floorf(nc.y), c0z = (int)floorf(nc.z);
    float fx = nc.x - (float)c0x, fy = nc.y - (float)c0y, fz = nc.z - (float)c0z;
    int c1x = min(c0x + 1, RR - 1), c1y = min(c0y + 1, RR - 1), c1z = min(c0z + 1, RR - 1);

    float4 acc = make_float4(0.f, 0.f, 0.f, 0.f);
    const __half* gb = g_grid2h + (size_t)b * R3 * CO;
#pragma unroll
    for (int corner = 0; corner < 8; corner++) {
        int ix = (corner & 4) ? c1x : c0x;
        int iy = (corner & 2) ? c1y : c0y;
        int iz = (corner & 1) ? c1z : c0z;
        float wg = ((corner & 4) ? fx : 1.f - fx) *
                   ((corner & 2) ? fy : 1.f - fy) *
                   ((corner & 1) ? fz : 1.f - fz);
        const uint2* row = (const uint2*)(gb + (size_t)(ix * RR2 + iy * RR + iz) * CO);
        uint2 v = __ldg(row + lane);
        float2 f0 = __half22float2(*(__half2*)&v.x);
        float2 f1 = __half22float2(*(__half2*)&v.y);
        acc.x += wg * f0.x; acc.y += wg * f0.y;
        acc.z += wg * f1.x; acc.w += wg * f1.y;
    }

    float4 pacc = make_float4(0.f, 0.f, 0.f, 0.f);
    const float* fp = feat + (size_t)warp * CI1;
#pragma unroll 8
    for (int k = 0; k < CI1; k++) {
        float fv = __ldg(fp + k);
        float4 w4 = __ldg((const float4*)(pw + (size_t)k * CO) + lane);
        pacc.x += fv * w4.x; pacc.y += fv * w4.y;
        pacc.z += fv * w4.z; pacc.w += fv * w4.w;
    }

    float pr[4] = {pacc.x, pacc.y, pacc.z, pacc.w};
    float vr[4] = {acc.x, acc.y, acc.z, acc.w};
    float4 o;
#pragma unroll
    for (int j = 0; j < 4; j++) {
        int co = lane * 4 + j;
        float s = pg[co] * rsqrtf(pv[co] + 1e-5f);
        float val = (pr[j] + pb[co] - pm[co]) * s + pbb[co];
        val = fmaxf(val, 0.f);
        ((float*)&o)[j] = vr[j] + val;
    }
    *((float4*)(out + (size_t)warp * CO) + lane) = o;
}

// ---------------- 8. coords tail copy ----------------
__global__ void copy_coords_kernel(const float* __restrict__ c, float* __restrict__ out) {
    int i = blockIdx.x * blockDim.x + threadIdx.x;
    if (i < BB * NPTS * 3) out[i] = c[i];
}

// ---------------- launch ----------------
extern "C" void kernel_launch(void* const* d_in, const int* in_sizes, int n_in,
                              void* d_out, int out_size) {
    const float* feat   = (const float*)d_in[0];
    const float* coords = (const float*)d_in[1];
    const float* c1w = (const float*)d_in[2];
    const float* c1b = (const float*)d_in[3];
    const float* b1g = (const float*)d_in[4];
    const float* b1b = (const float*)d_in[5];
    const float* b1m = (const float*)d_in[6];
    const float* b1v = (const float*)d_in[7];
    const float* c2w = (const float*)d_in[8];
    const float* c2b = (const float*)d_in[9];
    const float* b2g = (const float*)d_in[10];
    const float* b2b = (const float*)d_in[11];
    const float* b2m = (const float*)d_in[12];
    const float* b2v = (const float*)d_in[13];
    const float* pw  = (const float*)d_in[14];
    const float* pb  = (const float*)d_in[15];
    const float* pg  = (const float*)d_in[16];
    const float* pbb = (const float*)d_in[17];
    const float* pm  = (const float*)d_in[18];
    const float* pv  = (const float*)d_in[19];
    float* out = (float*)d_out;

    __half* pW1h;
    __half* pW2h;
    cudaGetSymbolAddress((void**)&pW1h, g_w1h);
    cudaGetSymbolAddress((void**)&pW2h, g_w2h);

    cudaFuncSetAttribute((const void*)conv_mma_kernel<CI1, true>,
                         cudaFuncAttributeMaxDynamicSharedMemorySize, DSMEM);
    cudaFuncSetAttribute((const void*)conv_mma_kernel<CO, false>,
                         cudaFuncAttributeMaxDynamicSharedMemorySize, DSMEM);

    stats_kernel<<<BB, 256>>>(coords);
    zero_kernel<<<2048, 256>>>();
    scatter_kernel<<<(BB * NPTS * 4 + 255) / 256, 256>>>(feat, coords);
    finalize_kernel<<<2048, 256>>>();
    wprep_kernel<CI1><<<(27 * CI1 * CO + 255) / 256, 256>>>(c1w, pW1h);
    wprep_kernel<CO><<<(27 * CO * CO + 255) / 256, 256>>>(c2w, pW2h);
    conv_mma_kernel<CI1, true><<<dim3(RR, RR / 4, BB), 256, DSMEM>>>(
        c1b, b1g, b1b, b1m, b1v);
    conv_mma_kernel<CO, false><<<dim3(RR, RR / 4, BB), 256, DSMEM>>>(
        c2b, b2g, b2b, b2m, b2v);
    devox_kernel<<<(BB * NPTS) / 8, 256>>>(coords, feat, pw, pb, pg, pbb, pm, pv, out);
    copy_coords_kernel<<<(BB * NPTS * 3 + 255) / 256, 256>>>(
        coords, out + (size_t)BB * NPTS * CO);
}

// round 11
// speedup vs baseline: 8.2419x; 1.0425x over previous
#include <cuda_runtime.h>
#include <cuda_fp16.h>
#include <cstdint>

// ---------------- problem constants ----------------
#define BB    4
#define NPTS  16384
#define CI1   64
#define CO    128
#define RR    32
#define RR2   (RR*RR)
#define R3    (RR*RR*RR)
#define NVOX  (BB*R3)

// ---------------- conv tiling ----------------
#define APITCH   40                         // halves per smem row (80B), conflict-free
#define AROWS    (3*6*34)                   // 612 halo rows (dx, y-halo, z-halo)
#define A_BYTES  (AROWS * APITCH * 2)       // 48960
#define NBUF_B   4
#define B_WARP   (32 * APITCH * 2)          // 2560 B: one warp-group's 32 B rows
#define B_BYTES  (4 * NBUF_B * B_WARP)      // 40960 (4 wn-groups x 4 buffers)
#define DSMEM    (A_BYTES + B_BYTES)        // 89920

// ---------------- device scratch ----------------
__device__ __align__(1024) float  g_stat[BB][4];
__device__ __align__(1024) float  g_cnt[NVOX];
__device__ __align__(1024) float  g_sums[(size_t)NVOX * CI1];     // fp32 scatter target
__device__ __align__(1024) __half g_sums_h[(size_t)NVOX * CI1];   // fp16 conv1 input
__device__ __align__(1024) __half g_w1h[27 * CO * CI1];           // [tap][co][ci] fp16
__device__ __align__(1024) __half g_w2h[27 * CO * CO];
__device__ __align__(1024) __half g_grid1h[(size_t)NVOX * CO];    // conv1 out (fp16)
__device__ __align__(1024) __half g_grid2h[(size_t)NVOX * CO];    // conv2 out (fp16)

// ---------------- PTX helpers ----------------
__device__ __forceinline__ uint32_t smem_u32(const void* p) {
    uint32_t a;
    asm("{ .reg .u64 t; cvta.to.shared.u64 t, %1; cvt.u32.u64 %0, t; }" : "=r"(a) : "l"(p));
    return a;
}

__device__ __forceinline__ void cp_async16(uint32_t dst, const void* src, uint32_t sz) {
    asm volatile("cp.async.cg.shared.global [%0], [%1], 16, %2;"
                 :: "r"(dst), "l"(src), "r"(sz) : "memory");
}
#define CP_COMMIT() asm volatile("cp.async.commit_group;" ::: "memory")
#define CP_WAIT0()  asm volatile("cp.async.wait_group 0;" ::: "memory")
#define CP_WAIT1()  asm volatile("cp.async.wait_group 1;" ::: "memory")
#define CP_WAIT2()  asm volatile("cp.async.wait_group 2;" ::: "memory")
#define CP_WAIT3()  asm volatile("cp.async.wait_group 3;" ::: "memory")

__device__ __forceinline__ void ldsm_x4(uint32_t* r, uint32_t addr) {
    asm volatile("ldmatrix.sync.aligned.m8n8.x4.shared.b16 {%0,%1,%2,%3}, [%4];"
                 : "=r"(r[0]), "=r"(r[1]), "=r"(r[2]), "=r"(r[3]) : "r"(addr));
}
__device__ __forceinline__ void ldsm_x2(uint32_t* r, uint32_t addr) {
    asm volatile("ldmatrix.sync.aligned.m8n8.x2.shared.b16 {%0,%1}, [%2];"
                 : "=r"(r[0]), "=r"(r[1]) : "r"(addr));
}

__device__ __forceinline__ void mma16816(float* d, const uint32_t* a, const uint32_t* b) {
    asm volatile(
        "mma.sync.aligned.m16n8k16.row.col.f32.f16.f16.f32 "
        "{%0,%1,%2,%3}, {%4,%5,%6,%7}, {%8,%9}, {%0,%1,%2,%3};"
        : "+f"(d[0]), "+f"(d[1]), "+f"(d[2]), "+f"(d[3])
        : "r"(a[0]), "r"(a[1]), "r"(a[2]), "r"(a[3]), "r"(b[0]), "r"(b[1]));
}

// ---------------- nc helper ----------------
__device__ __forceinline__ float3 compute_nc(const float* cp, int b) {
    float denom = g_stat[b][3];
    float nx = ((cp[0] - g_stat[b][0]) / denom + 0.5f) * (float)RR;
    float ny = ((cp[1] - g_stat[b][1]) / denom + 0.5f) * (float)RR;
    float nz = ((cp[2] - g_stat[b][2]) / denom + 0.5f) * (float)RR;
    nx = fminf(fmaxf(nx, 0.f), (float)(RR - 1));
    ny = fminf(fmaxf(ny, 0.f), (float)(RR - 1));
    nz = fminf(fmaxf(nz, 0.f), (float)(RR - 1));
    return make_float3(nx, ny, nz);
}

// ---------------- 1. stats ----------------
__global__ void stats_kernel(const float* __restrict__ coords) {
    int b = blockIdx.x;
    const float* c = coords + (size_t)b * NPTS * 3;
    float sx = 0.f, sy = 0.f, sz = 0.f;
    for (int i = threadIdx.x; i < NPTS; i += blockDim.x) {
        sx += c[3 * i + 0]; sy += c[3 * i + 1]; sz += c[3 * i + 2];
    }
    __shared__ float red[4][32];
    int lane = threadIdx.x & 31, w = threadIdx.x >> 5;
    for (int o = 16; o; o >>= 1) {
        sx += __shfl_down_sync(0xffffffffu, sx, o);
        sy += __shfl_down_sync(0xffffffffu, sy, o);
        sz += __shfl_down_sync(0xffffffffu, sz, o);
    }
    if (lane == 0) { red[0][w] = sx; red[1][w] = sy; red[2][w] = sz; }
    __syncthreads();
    int nw = blockDim.x >> 5;
    if (threadIdx.x == 0) {
        float tx = 0.f, ty = 0.f, tz = 0.f;
        for (int i = 0; i < nw; i++) { tx += red[0][i]; ty += red[1][i]; tz += red[2][i]; }
        red[0][0] = tx / (float)NPTS; red[1][0] = ty / (float)NPTS; red[2][0] = tz / (float)NPTS;
    }
    __syncthreads();
    float mx = red[0][0], my = red[1][0], mz = red[2][0];
    float mval = 0.f;
    for (int i = threadIdx.x; i < NPTS; i += blockDim.x) {
        float dx = c[3 * i + 0] - mx, dy = c[3 * i + 1] - my, dz = c[3 * i + 2] - mz;
        mval = fmaxf(mval, sqrtf(dx * dx + dy * dy + dz * dz));
    }
    for (int o = 16; o; o >>= 1)
        mval = fmaxf(mval, __shfl_down_sync(0xffffffffu, mval, o));
    if (lane == 0) red[3][w] = mval;
    __syncthreads();
    if (threadIdx.x == 0) {
        float t = 0.f;
        for (int i = 0; i < nw; i++) t = fmaxf(t, red[3][i]);
        g_stat[b][0] = mx; g_stat[b][1] = my; g_stat[b][2] = mz;
        g_stat[b][3] = t * 2.f + 1e-6f;
    }
}

// ---------------- 2. zero ----------------
__global__ void zero_kernel() {
    size_t stride = (size_t)gridDim.x * blockDim.x;
    size_t tid = (size_t)blockIdx.x * blockDim.x + threadIdx.x;
    float4 z4 = make_float4(0.f, 0.f, 0.f, 0.f);
    float4* s4 = (float4*)g_sums;
    for (size_t i = tid; i < (size_t)NVOX * (CI1 / 4); i += stride) s4[i] = z4;
    for (size_t i = tid; i < (size_t)NVOX; i += stride) g_cnt[i] = 0.f;
}

// ---------------- 3. scatter ----------------
__global__ void scatter_kernel(const float* __restrict__ feat,
                               const float* __restrict__ coords) {
    int gid = blockIdx.x * blockDim.x + threadIdx.x;
    if (gid >= BB * NPTS * 4) return;
    int pt = gid >> 2, q = gid & 3;
    int b = pt / NPTS;
    float3 nc = compute_nc(coords + (size_t)pt * 3, b);
    int vx = __float2int_rn(nc.x), vy = __float2int_rn(nc.y), vz = __float2int_rn(nc.z);
    int lin = b * R3 + vx * RR2 + vy * RR + vz;
    const float4* f = (const float4*)(feat + (size_t)pt * CI1 + q * 16);
    float* dst = g_sums + (size_t)lin * CI1 + q * 16;
#pragma unroll
    for (int j = 0; j < 4; j++) {
        float4 v = __ldg(f + j);
        atomicAdd(dst + 4 * j + 0, v.x);
        atomicAdd(dst + 4 * j + 1, v.y);
        atomicAdd(dst + 4 * j + 2, v.z);
        atomicAdd(dst + 4 * j + 3, v.w);
    }
    if (q == 0) atomicAdd(g_cnt + lin, 1.f);
}

// ---------------- 4. finalize: divide + fp16 convert ----------------
__global__ void finalize_kernel() {
    size_t stride = (size_t)gridDim.x * blockDim.x;
    size_t total = (size_t)NVOX * (CI1 / 4);
    __half2* oh = (__half2*)g_sums_h;
    for (size_t i = (size_t)blockIdx.x * blockDim.x + threadIdx.x; i < total; i += stride) {
        float cn = g_cnt[i >> 4];
        float inv = cn > 0.f ? 1.f / cn : 1.f;
        float4 v = ((float4*)g_sums)[i];
        oh[2 * i + 0] = __floats2half2_rn(v.x * inv, v.y * inv);
        oh[2 * i + 1] = __floats2half2_rn(v.z * inv, v.w * inv);
    }
}

// ---------------- 5. weight prep: [tap][ci][co] -> [tap][co][ci] fp16 ----------------
template <int CI>
__global__ void wprep_kernel(const float* __restrict__ w, __half* __restrict__ wt) {
    int idx = blockIdx.x * blockDim.x + threadIdx.x;
    if (idx >= 27 * CI * CO) return;
    int t = idx / (CI * CO);
    int rem = idx - t * (CI * CO);
    int co = rem / CI;
    int ci = rem - co * CI;
    wt[idx] = __float2half_rn(__ldg(&w[((size_t)t * CI + ci) * CO + co]));
}

// ---------------- 6. fp16 mma.sync implicit-GEMM Conv3D ----------------
// Halo-resident A (per ci-chunk), warp-autonomous B pipeline (per-warp cp.async
// groups, 4-deep ring per wn-group, wm-pair coupled by named barrier), ldmatrix
// fragment loads. CTA barriers only at ci-chunk boundaries.
template <int CI, bool FIRST>
__global__ void __launch_bounds__(256, 2) conv_mma_kernel(
    const float* __restrict__ cb, const float* __restrict__ bg,
    const float* __restrict__ bb, const float* __restrict__ bm,
    const float* __restrict__ bv) {
    constexpr int KC = CI / 32;
    const __half* in = FIRST ? g_sums_h : g_grid1h;
    const __half* wt = FIRST ? g_w1h : g_w2h;

    extern __shared__ char dsm[];
    __shared__ float s_scale[CO], s_shift[CO];

    int tid = threadIdx.x, lane = tid & 31, wid = tid >> 5;
    int gID = lane >> 2, tig = lane & 3;
    int wm = wid >> 2, wn = wid & 3;
    int x = blockIdx.x, y0 = blockIdx.y * 4, b = blockIdx.z;
    size_t bbase = (size_t)b * R3;

    if (tid < CO) {
        float s = bg[tid] * rsqrtf(bv[tid] + 1e-4f);
        s_scale[tid] = s;
        s_shift[tid] = (cb[tid] - bm[tid]) * s + bb[tid];
    }

    uint32_t aB = smem_u32(dsm);
    uint32_t bB = aB + A_BYTES;

    // per-lane ldmatrix address pre-computation (tap-independent)
    int rlane = (lane & 7) + ((lane >> 3) & 1) * 8;
    uint32_t koffA = ((lane >> 4) & 1) * 16;
    uint32_t preA[4];
#pragma unroll
    for (int mt = 0; mt < 4; mt++) {
        int r = wm * 64 + mt * 16 + rlane;
        preA[mt] = (uint32_t)(((r >> 5) * 34 + (r & 31)) * (APITCH * 2)) + koffA;
    }
    int ll = lane & 15;
    uint32_t browoff[4];
#pragma unroll
    for (int nt = 0; nt < 4; nt++)
        browoff[nt] = (uint32_t)((nt * 8 + (ll & 7)) * (APITCH * 2) + ((ll >> 3) & 1) * 16);

    auto issueA = [&](int cc) {
        for (int i = tid; i < AROWS * 4; i += 256) {
            int row = i >> 2, c4 = i & 3;
            int dxp = row / 204, rem = row - dxp * 204;
            int yl = rem / 34, zl = rem - yl * 34;
            int gx = x + dxp - 1, gy = y0 + yl - 1, gz = zl - 1;
            bool ok = ((unsigned)gx < RR) && ((unsigned)gy < RR) && ((unsigned)gz < RR);
            int gxc = ok ? gx : 0, gyc = ok ? gy : 0, gzc = ok ? gz : 0;
            const __half* src = in +
                ((size_t)(bbase + gxc * RR2 + gyc * RR + gzc)) * CI + cc * 32 + c4 * 8;
            cp_async16(aB + row * (APITCH * 2) + c4 * 16, src, ok ? 16u : 0u);
        }
        CP_COMMIT();
    };

    // per-warp B load: this warp's 32 rows (wn-group), own commit group
    auto issueB = [&](int g) {
        int tap = g % 27, cc = g / 27;
        uint32_t dst = bB + (wn * NBUF_B + (g & (NBUF_B - 1))) * B_WARP;
#pragma unroll
        for (int it = 0; it < 4; it++) {
            int idx = lane + it * 32;
            int row = idx >> 2, c4 = idx & 3;
            const __half* src = wt + ((size_t)tap * CO + wn * 32 + row) * CI + cc * 32 + c4 * 8;
            cp_async16(dst + row * (APITCH * 2) + c4 * 16, src, 16u);
        }
        CP_COMMIT();
    };

    float d[4][4][4];
#pragma unroll
    for (int mt = 0; mt < 4; mt++)
#pragma unroll
        for (int nt = 0; nt < 4; nt++)
#pragma unroll
            for (int r = 0; r < 4; r++) d[mt][nt][r] = 0.f;

    for (int cc = 0; cc < KC; cc++) {
        int g0 = cc * 27;
        __syncthreads();                         // old A fully consumed
        issueA(cc);
        issueB(g0); issueB(g0 + 1); issueB(g0 + 2);
        CP_WAIT3();                              // own A copies done (3 B groups newer)
        __syncthreads();                         // A visible CTA-wide

        for (int tap = 0; tap < 27; tap++) {
            int g = g0 + tap;
            if (tap <= 24) CP_WAIT2();
            else if (tap == 25) CP_WAIT1();
            else CP_WAIT0();
            __syncwarp();

            int dxp = tap / 9, dyz = tap - dxp * 9, dy = dyz / 3, dz = dyz - dy * 3;
            uint32_t abase = aB + (uint32_t)((dxp * 204 + dy * 34 + dz) * (APITCH * 2));
            uint32_t bbuf = bB + (wn * NBUF_B + (g & (NBUF_B - 1))) * B_WARP;

            uint32_t a[2][4][4], bf[2][4][2];
#pragma unroll
            for (int kt = 0; kt < 2; kt++) {
#pragma unroll
                for (int mt = 0; mt < 4; mt++)
                    ldsm_x4(a[kt][mt], abase + preA[mt] + kt * 32);
#pragma unroll
                for (int nt = 0; nt < 4; nt++)
                    ldsm_x2(bf[kt][nt], bbuf + browoff[nt] + kt * 32);
            }
            // wm-pair barrier: both warps of this wn-group done reading before
            // either overwrites the g-3-old buffer with the g+3 prefetch.
            asm volatile("bar.sync %0, %1;" :: "r"(1 + wn), "r"(64) : "memory");
            if (tap < 24) issueB(g + 3);
#pragma unroll
            for (int kt = 0; kt < 2; kt++)
#pragma unroll
                for (int mt = 0; mt < 4; mt++)
#pragma unroll
                    for (int nt = 0; nt < 4; nt++)
                        mma16816(d[mt][nt], a[kt][mt], bf[kt][nt]);
        }
    }

    // ---- epilogue: bias+BN fold + LeakyReLU, fp16 store ----
    __half* outp = FIRST ? g_grid1h : g_grid2h;
#pragma unroll
    for (int mt = 0; mt < 4; mt++) {
        int r0 = wm * 64 + mt * 16 + gID;
        int r1 = r0 + 8;
        size_t vox0 = bbase + (size_t)x * RR2 + (size_t)(y0 + (r0 >> 5)) * RR + (r0 & 31);
        size_t vox1 = bbase + (size_t)x * RR2 + (size_t)(y0 + (r1 >> 5)) * RR + (r1 & 31);
#pragma unroll
        for (int nt = 0; nt < 4; nt++) {
            int col = wn * 32 + nt * 8 + 2 * tig;
            float sc0 = s_scale[col], sh0 = s_shift[col];
            float sc1 = s_scale[col + 1], sh1 = s_shift[col + 1];
            float v00 = d[mt][nt][0] * sc0 + sh0;
            float v01 = d[mt][nt][1] * sc1 + sh1;
            float v10 = d[mt][nt][2] * sc0 + sh0;
            float v11 = d[mt][nt][3] * sc1 + sh1;
            v00 = v00 >= 0.f ? v00 : 0.1f * v00;
            v01 = v01 >= 0.f ? v01 : 0.1f * v01;
            v10 = v10 >= 0.f ? v10 : 0.1f * v10;
            v11 = v11 >= 0.f ? v11 : 0.1f * v11;
            *(__half2*)(outp + vox0 * CO + col) = __floats2half2_rn(v00, v01);
            *(__half2*)(outp + vox1 * CO + col) = __floats2half2_rn(v10, v11);
        }
    }
}

// ---------------- 7. devoxelize + point MLP ----------------
__global__ void devox_kernel(const float* __restrict__ coords,
                             const float* __restrict__ feat,
                             const float* __restrict__ pw,
                             const float* __restrict__ pb,
                             const float* __restrict__ pg,
                             const float* __restrict__ pbb,
                             const float* __restrict__ pm,
                             const float* __restrict__ pv,
                             float* __restrict__ out) {
    int warp = blockIdx.x * (blockDim.x >> 5) + (threadIdx.x >> 5);
    int lane = threadIdx.x & 31;
    if (warp >= BB * NPTS) return;
    int b = warp / NPTS;
    float3 nc = compute_nc(coords + (size_t)warp * 3, b);
    int c0x = (int)floorf(nc.x), c0y = (int)floorf(nc.y), c0z = (int)floorf(nc.z);
    float fx = nc.x - (float)c0x, fy = nc.y - (float)c0y, fz = nc.z - (float)c0z;
    int c1x = min(c0x + 1, RR - 1), c1y = min(c0y + 1, RR - 1), c1z = min(c0z + 1, RR - 1);

    float4 acc = make_float4(0.f, 0.f, 0.f, 0.f);
    const __half* gb = g_grid2h + (size_t)b * R3 * CO;
#pragma unroll
    for (int corner = 0; corner < 8; corner++) {
        int ix = (corner & 4) ? c1x : c0x;
        int iy = (corner & 2) ? c1y : c0y;
        int iz = (corner & 1) ? c1z : c0z;
        float wg = ((corner & 4) ? fx : 1.f - fx) *
                   ((corner & 2) ? fy : 1.f - fy) *
                   ((corner & 1) ? fz : 1.f - fz);
        const uint2* row = (const uint2*)(gb + (size_t)(ix * RR2 + iy * RR + iz) * CO);
        uint2 v = __ldg(row + lane);
        float2 f0 = __half22float2(*(__half2*)&v.x);
        float2 f1 = __half22float2(*(__half2*)&v.y);
        acc.x += wg * f0.x; acc.y += wg * f0.y;
        acc.z += wg * f1.x; acc.w += wg * f1.y;
    }

    float4 pacc = make_float4(0.f, 0.f, 0.f, 0.f);
    const float* fp = feat + (size_t)warp * CI1;
#pragma unroll 8
    for (int k = 0; k < CI1; k++) {
        float fv = __ldg(fp + k);
        float4 w4 = __ldg((const float4*)(pw + (size_t)k * CO) + lane);
        pacc.x += fv * w4.x; pacc.y += fv * w4.y;
        pacc.z += fv * w4.z; pacc.w += fv * w4.w;
    }

    float pr[4] = {pacc.x, pacc.y, pacc.z, pacc.w};
    float vr[4] = {acc.x, acc.y, acc.z, acc.w};
    float4 o;
#pragma unroll
    for (int j = 0; j < 4; j++) {
        int co = lane * 4 + j;
        float s = pg[co] * rsqrtf(pv[co] + 1e-5f);
        float val = (pr[j] + pb[co] - pm[co]) * s + pbb[co];
        val = fmaxf(val, 0.f);
        ((float*)&o)[j] = vr[j] + val;
    }
    *((float4*)(out + (size_t)warp * CO) + lane) = o;
}

// ---------------- 8. coords tail copy ----------------
__global__ void copy_coords_kernel(const float* __restrict__ c, float* __restrict__ out) {
    int i = blockIdx.x * blockDim.x + threadIdx.x;
    if (i < BB * NPTS * 3) out[i] = c[i];
}

// ---------------- launch ----------------
extern "C" void kernel_launch(void* const* d_in, const int* in_sizes, int n_in,
                              void* d_out, int out_size) {
    const float* feat   = (const float*)d_in[0];
    const float* coords = (const float*)d_in[1];
    const float* c1w = (const float*)d_in[2];
    const float* c1b = (const float*)d_in[3];
    const float* b1g = (const float*)d_in[4];
    const float* b1b = (const float*)d_in[5];
    const float* b1m = (const float*)d_in[6];
    const float* b1v = (const float*)d_in[7];
    const float* c2w = (const float*)d_in[8];
    const float* c2b = (const float*)d_in[9];
    const float* b2g = (const float*)d_in[10];
    const float* b2b = (const float*)d_in[11];
    const float* b2m = (const float*)d_in[12];
    const float* b2v = (const float*)d_in[13];
    const float* pw  = (const float*)d_in[14];
    const float* pb  = (const float*)d_in[15];
    const float* pg  = (const float*)d_in[16];
    const float* pbb = (const float*)d_in[17];
    const float* pm  = (const float*)d_in[18];
    const float* pv  = (const float*)d_in[19];
    float* out = (float*)d_out;

    __half* pW1h;
    __half* pW2h;
    cudaGetSymbolAddress((void**)&pW1h, g_w1h);
    cudaGetSymbolAddress((void**)&pW2h, g_w2h);

    cudaFuncSetAttribute((const void*)conv_mma_kernel<CI1, true>,
                         cudaFuncAttributeMaxDynamicSharedMemorySize, DSMEM);
    cudaFuncSetAttribute((const void*)conv_mma_kernel<CO, false>,
                         cudaFuncAttributeMaxDynamicSharedMemorySize, DSMEM);

    // order chosen so ncu (-s 5 -c 1) lands on conv1
    stats_kernel<<<BB, 256>>>(coords);
    zero_kernel<<<2048, 256>>>();
    scatter_kernel<<<(BB * NPTS * 4 + 255) / 256, 256>>>(feat, coords);
    wprep_kernel<CI1><<<(27 * CI1 * CO + 255) / 256, 256>>>(c1w, pW1h);
    finalize_kernel<<<2048, 256>>>();
    conv_mma_kernel<CI1, true><<<dim3(RR, RR / 4, BB), 256, DSMEM>>>(
        c1b, b1g, b1b, b1m, b1v);
    wprep_kernel<CO><<<(27 * CO * CO + 255) / 256, 256>>>(c2w, pW2h);
    conv_mma_kernel<CO, false><<<dim3(RR, RR / 4, BB), 256, DSMEM>>>(
        c2b, b2g, b2b, b2m, b2v);
    devox_kernel<<<(BB * NPTS) / 8, 256>>>(coords, feat, pw, pb, pg, pbb, pm, pv, out);
    copy_coords_kernel<<<(BB * NPTS * 3 + 255) / 256, 256>>>(
        coords, out + (size_t)BB * NPTS * CO);
}